// round 15
// baseline (speedup 1.0000x reference)
#include <cuda_runtime.h>
#include <cuda_bf16.h>

#define BATCH 2
#define SEQ   2048
#define DM    1024
#define NH    16
#define DH    64
#define KS    32

#define MROWS (BATCH*SEQ)   // 4096
#define FULLM 0xffffffffu
#define NTRI  136

// ---------------- scratch ----------------------------------------------------
__device__ float g_Q [BATCH*SEQ*DM];
__device__ float g_K [BATCH*SEQ*DM];
__device__ float g_V [BATCH*SEQ*DM];
__device__ float g_HO[BATCH*SEQ*DM];
__device__ float g_WGT[BATCH*NH*SEQ*KS];
__device__ int   g_IDX[BATCH*NH*SEQ*KS];
__device__ float g_SC[(size_t)BATCH*NH*SEQ*SEQ];

__device__ __forceinline__ float neg_inf() { return __int_as_float(0xff800000); }

// ---------------- 64x64-tile fp32 GEMM core: C = A @ W^T + bias --------------
// 256 threads, 4x4 microtile, BK=16 double-buffered. Ascending-k accumulation
// per output element -> bitwise-identical to the 128x128 version.
#define BK2 16

__device__ __forceinline__ void gemm64_tile(
    const float* __restrict__ A, const float* __restrict__ W,
    const float* __restrict__ bias, float* __restrict__ C,
    int M, int N, int K, int bm, int bn)
{
    __shared__ float As[2][BK2][64];
    __shared__ float Ws[2][BK2][64];
    const int tid = threadIdx.x;
    const int tx = tid & 15, ty = tid >> 4;

    float acc[4][4];
#pragma unroll
    for (int i = 0; i < 4; i++)
#pragma unroll
        for (int j = 0; j < 4; j++) acc[i][j] = 0.f;

    const int lr = tid >> 2;            // 0..63
    const int lc = (tid & 3) * 4;       // 0,4,8,12

    const float* Ap = A + (size_t)(bm + lr) * K + lc;
    const float* Wp = W + (size_t)(bn + lr) * K + lc;

    float4 pa = *(const float4*)(Ap);
    float4 pw = *(const float4*)(Wp);

    As[0][lc+0][lr]=pa.x; As[0][lc+1][lr]=pa.y; As[0][lc+2][lr]=pa.z; As[0][lc+3][lr]=pa.w;
    Ws[0][lc+0][lr]=pw.x; Ws[0][lc+1][lr]=pw.y; Ws[0][lc+2][lr]=pw.z; Ws[0][lc+3][lr]=pw.w;
    __syncthreads();

    const int ntile = K / BK2;
    for (int t = 0; t < ntile; t++) {
        const int buf = t & 1;
        const bool more = (t + 1 < ntile);
        if (more) {
            pa = *(const float4*)(Ap + (t + 1) * BK2);
            pw = *(const float4*)(Wp + (t + 1) * BK2);
        }
#pragma unroll
        for (int kk = 0; kk < BK2; kk++) {
            float4 a4 = *(const float4*)&As[buf][kk][ty*4];
            float4 w4 = *(const float4*)&Ws[buf][kk][tx*4];
            float a[4] = {a4.x, a4.y, a4.z, a4.w};
            float w[4] = {w4.x, w4.y, w4.z, w4.w};
#pragma unroll
            for (int i = 0; i < 4; i++)
#pragma unroll
                for (int j = 0; j < 4; j++)
                    acc[i][j] += a[i] * w[j];
        }
        if (more) {
            const int nb = buf ^ 1;
            As[nb][lc+0][lr]=pa.x; As[nb][lc+1][lr]=pa.y; As[nb][lc+2][lr]=pa.z; As[nb][lc+3][lr]=pa.w;
            Ws[nb][lc+0][lr]=pw.x; Ws[nb][lc+1][lr]=pw.y; Ws[nb][lc+2][lr]=pw.z; Ws[nb][lc+3][lr]=pw.w;
        }
        __syncthreads();
    }

    float4 b4 = *(const float4*)(bias + bn + tx*4);
    float bb[4] = {b4.x, b4.y, b4.z, b4.w};

#pragma unroll
    for (int i = 0; i < 4; i++) {
        int m = bm + ty*4 + i;
        *(float4*)(C + (size_t)m * N + bn + tx*4) =
            make_float4(acc[i][0]+bb[0], acc[i][1]+bb[1],
                        acc[i][2]+bb[2], acc[i][3]+bb[3]);
    }
}

// ---------------- fused QKV projection (grid.z selects Q/K/V) ----------------
__global__ __launch_bounds__(256) void qkv_kernel(
    const float* __restrict__ x,
    const float* __restrict__ Wq, const float* __restrict__ bq, float* __restrict__ Qo,
    const float* __restrict__ Wk, const float* __restrict__ bk, float* __restrict__ Ko,
    const float* __restrict__ Wv, const float* __restrict__ bv, float* __restrict__ Vo)
{
    const float* W; const float* bias; float* C;
    if (blockIdx.z == 0)      { W = Wq; bias = bq; C = Qo; }
    else if (blockIdx.z == 1) { W = Wk; bias = bk; C = Ko; }
    else                      { W = Wv; bias = bv; C = Vo; }
    gemm64_tile(x, W, bias, C, MROWS, DM, DM,
                blockIdx.y * 64, blockIdx.x * 64);
}

// ---------------- single GEMM (output projection) ----------------------------
__global__ __launch_bounds__(256) void gemm_kernel(
    const float* __restrict__ A, const float* __restrict__ W,
    const float* __restrict__ bias, float* __restrict__ C,
    int M, int N, int K)
{
    gemm64_tile(A, W, bias, C, M, N, K, blockIdx.y * 64, blockIdx.x * 64);
}

// ---------------- score GEMM: S[q,k] = (Q_row_q . K_row_k) / 8 ---------------
// One block per lower-triangular 128x128 tile of one (b,h). K-dim = 64.
#define BM 128
#define BN 128

__global__ __launch_bounds__(256) void score_kernel(
    const float* __restrict__ Q, const float* __restrict__ Kg,
    float* __restrict__ SC)
{
    __shared__ float As[16][BM];
    __shared__ float Ws[16][BN];

    const int t = blockIdx.x;
    const int h = blockIdx.y, b = blockIdx.z;
    int qt = (int)((sqrtf(8.f * t + 1.f) - 1.f) * 0.5f);
    while ((qt + 1) * (qt + 2) / 2 <= t) qt++;
    while (qt * (qt + 1) / 2 > t) qt--;
    int kt = t - qt * (qt + 1) / 2;

    const int tid = threadIdx.x;
    const int tx = tid & 15, ty = tid >> 4;
    const int bm = qt * BM, bn = kt * BN;

    float acc[8][8];
#pragma unroll
    for (int i = 0; i < 8; i++)
#pragma unroll
        for (int j = 0; j < 8; j++) acc[i][j] = 0.f;

    const float* Qb = Q  + (size_t)b*SEQ*DM + h*DH;
    const float* Kb = Kg + (size_t)b*SEQ*DM + h*DH;

    int lr = tid >> 1;            // 0..127
    int lc = (tid & 1) * 8;       // 0 or 8

    for (int k0 = 0; k0 < DH; k0 += 16) {
        float4 a0 = *(const float4*)(Qb + (size_t)(bm + lr) * DM + k0 + lc);
        float4 a1 = *(const float4*)(Qb + (size_t)(bm + lr) * DM + k0 + lc + 4);
        float4 w0 = *(const float4*)(Kb + (size_t)(bn + lr) * DM + k0 + lc);
        float4 w1 = *(const float4*)(Kb + (size_t)(bn + lr) * DM + k0 + lc + 4);
        As[lc+0][lr]=a0.x; As[lc+1][lr]=a0.y; As[lc+2][lr]=a0.z; As[lc+3][lr]=a0.w;
        As[lc+4][lr]=a1.x; As[lc+5][lr]=a1.y; As[lc+6][lr]=a1.z; As[lc+7][lr]=a1.w;
        Ws[lc+0][lr]=w0.x; Ws[lc+1][lr]=w0.y; Ws[lc+2][lr]=w0.z; Ws[lc+3][lr]=w0.w;
        Ws[lc+4][lr]=w1.x; Ws[lc+5][lr]=w1.y; Ws[lc+6][lr]=w1.z; Ws[lc+7][lr]=w1.w;
        __syncthreads();
#pragma unroll
        for (int kk = 0; kk < 16; kk++) {
            float4 q0 = *(const float4*)&As[kk][ty*4];
            float4 q1 = *(const float4*)&As[kk][64 + ty*4];
            float4 k0v = *(const float4*)&Ws[kk][tx*4];
            float4 k1v = *(const float4*)&Ws[kk][64 + tx*4];
            float a[8] = {q0.x,q0.y,q0.z,q0.w,q1.x,q1.y,q1.z,q1.w};
            float w[8] = {k0v.x,k0v.y,k0v.z,k0v.w,k1v.x,k1v.y,k1v.z,k1v.w};
#pragma unroll
            for (int i = 0; i < 8; i++)
#pragma unroll
                for (int j = 0; j < 8; j++)
                    acc[i][j] += a[i] * w[j];
        }
        __syncthreads();
    }

    float* Sb = SC + (((size_t)b*NH + h)*SEQ) * SEQ;
#pragma unroll
    for (int i = 0; i < 8; i++) {
        int m = bm + ((i < 4) ? (ty*4 + i) : (64 + ty*4 + i - 4));
        float4 o0 = make_float4(acc[i][0]*.125f, acc[i][1]*.125f, acc[i][2]*.125f, acc[i][3]*.125f);
        float4 o1 = make_float4(acc[i][4]*.125f, acc[i][5]*.125f, acc[i][6]*.125f, acc[i][7]*.125f);
        *(float4*)(Sb + (size_t)m * SEQ + bn + tx*4)      = o0;
        *(float4*)(Sb + (size_t)m * SEQ + bn + 64 + tx*4) = o1;
    }
}

// ---------------- selection: streaming top-32 (pipelined f4) + softmax + AV --
__global__ __launch_bounds__(256) void select_kernel(
    const float* __restrict__ SC, const float* __restrict__ Vg,
    float* __restrict__ HO, float* __restrict__ WGT, int* __restrict__ IDX)
{
    const int h = blockIdx.y, b = blockIdx.z;
    const int tid = threadIdx.x;
    const int lane = tid & 31, wid = tid >> 5;
    const int q = blockIdx.x * 8 + wid;
    const float NEG = neg_inf();

    const float* row = SC + ((((size_t)b*NH + h)*SEQ) + q) * SEQ;

    float sv = NEG;
    int   si = 0x7fffffff;
    float minv = NEG;
    int   mini = 0x7fffffff;

    const int total = q + 1;
    const int ngrp = total >> 7;              // full 128-key groups

    float4 cur;
    if (ngrp > 0) cur = *(const float4*)(row + lane * 4);

    for (int g = 0; g < ngrp; g++) {
        float4 nxt;
        if (g + 1 < ngrp)
            nxt = *(const float4*)(row + (g + 1) * 128 + lane * 4);
        const int base = g * 128 + lane * 4;
#pragma unroll
        for (int j = 0; j < 4; j++) {
            float v = (j == 0) ? cur.x : (j == 1) ? cur.y : (j == 2) ? cur.z : cur.w;
            int ii = base + j;
            bool contend = (v > minv) || (v == minv && ii < mini);
            unsigned m = __ballot_sync(FULLM, contend);
            if (m) {
                do {
                    int src = __ffs(m) - 1; m &= m - 1;
                    float nv = __shfl_sync(FULLM, v,  src);
                    int   ni = __shfl_sync(FULLM, ii, src);
                    bool better = (nv < sv) || (nv == sv && si < ni);  // sv better
                    unsigned bm2 = __ballot_sync(FULLM, better);
                    int p = __popc(bm2);
                    float upv = __shfl_up_sync(FULLM, sv, 1);
                    int   upi = __shfl_up_sync(FULLM, si, 1);
                    if (lane == p)      { sv = nv;  si = ni;  }
                    else if (lane > p)  { sv = upv; si = upi; }
                } while (m);
                minv = __shfl_sync(FULLM, sv, 31);
                mini = __shfl_sync(FULLM, si, 31);
            }
        }
        cur = nxt;
    }

    // tail: keys [ngrp*128, total)
    for (int k0 = ngrp << 7; k0 < total; k0 += 32) {
        int k = k0 + lane;
        float v = NEG; int ii = 0x7fffffff;
        if (k < total) { v = row[k]; ii = k; }

        bool contend = (v > minv) || (v == minv && v != NEG && ii < mini);
        unsigned m = __ballot_sync(FULLM, contend);
        if (m) {
            do {
                int src = __ffs(m) - 1; m &= m - 1;
                float nv = __shfl_sync(FULLM, v,  src);
                int   ni = __shfl_sync(FULLM, ii, src);
                bool better = (sv > nv) || (sv == nv && si < ni);
                unsigned bm2 = __ballot_sync(FULLM, better);
                int p = __popc(bm2);
                float upv = __shfl_up_sync(FULLM, sv, 1);
                int   upi = __shfl_up_sync(FULLM, si, 1);
                if (lane == p)      { sv = nv;  si = ni;  }
                else if (lane > p)  { sv = upv; si = upi; }
            } while (m);
            minv = __shfl_sync(FULLM, sv, 31);
            mini = __shfl_sync(FULLM, si, 31);
        }
    }

    // softmax over selected (sorted descending; lane 0 = max, finite)
    bool valid = (sv != NEG);
    float mx = __shfl_sync(FULLM, sv, 0);
    float e = valid ? expf(sv - mx) : 0.f;
    float tot = e;
#pragma unroll
    for (int o = 16; o; o >>= 1) tot += __shfl_xor_sync(FULLM, tot, o);
    float w = e / tot;
    int iw = valid ? si : -1;

    size_t off = ((((size_t)b*NH + h)*SEQ) + (size_t)q) * KS + lane;
    WGT[off] = w;
    IDX[off] = iw;

    // AV: each lane owns dims (lane, lane+32)
    const float* Vb = Vg + (size_t)b*SEQ*DM + h*DH;
    float acc0 = 0.f, acc1 = 0.f;
#pragma unroll
    for (int j = 0; j < KS; j++) {
        float wj = __shfl_sync(FULLM, w, j);
        int   ij = __shfl_sync(FULLM, iw, j);
        if (ij >= 0) {
            const float* vr = Vb + (size_t)ij * DM;
            acc0 += wj * vr[lane];
            acc1 += wj * vr[lane + 32];
        }
    }
    float* out = HO + ((size_t)(b*SEQ + q)) * DM + h*DH;
    out[lane]      = acc0;
    out[lane + 32] = acc1;
}

// ---------------- mean over heads -> dense [B, SEQ, SEQ] ---------------------
__global__ __launch_bounds__(256) void mean_kernel(
    const float* __restrict__ WGT, const int* __restrict__ IDX,
    float* __restrict__ out_attn)
{
    __shared__ float row[SEQ];
    const int q = blockIdx.x, b = blockIdx.y;
    const int tid = threadIdx.x;
    for (int i = tid; i < SEQ; i += 256) row[i] = 0.f;
    __syncthreads();
    for (int h = 0; h < NH; h++) {
        if (tid < KS) {
            size_t off = ((((size_t)b*NH + h)*SEQ) + q) * KS + tid;
            float w = WGT[off];
            int k = IDX[off];
            if (k >= 0 && w > 0.f) row[k] += w * (1.0f / NH);
        }
        __syncthreads();
    }
    float* o = out_attn + ((size_t)b*SEQ + q) * SEQ;
    for (int i = tid; i < SEQ; i += 256) o[i] = row[i];
}

// ---------------- launch -----------------------------------------------------
extern "C" void kernel_launch(void* const* d_in, const int* in_sizes, int n_in,
                              void* d_out, int out_size)
{
    const float* x  = (const float*)d_in[0];
    const float* Wq = (const float*)d_in[1];
    const float* bq = (const float*)d_in[2];
    const float* Wk = (const float*)d_in[3];
    const float* bk = (const float*)d_in[4];
    const float* Wv = (const float*)d_in[5];
    const float* bv = (const float*)d_in[6];
    const float* Wo = (const float*)d_in[7];
    const float* bo = (const float*)d_in[8];

    float *Qp, *Kp, *Vp, *HOp, *Wp, *Sp; int* Ip;
    cudaGetSymbolAddress((void**)&Qp,  g_Q);
    cudaGetSymbolAddress((void**)&Kp,  g_K);
    cudaGetSymbolAddress((void**)&Vp,  g_V);
    cudaGetSymbolAddress((void**)&HOp, g_HO);
    cudaGetSymbolAddress((void**)&Wp,  g_WGT);
    cudaGetSymbolAddress((void**)&Ip,  g_IDX);
    cudaGetSymbolAddress((void**)&Sp,  g_SC);

    dim3 g64(DM / 64, MROWS / 64);          // (16, 64) = 1024 blocks

    qkv_kernel<<<dim3(DM / 64, MROWS / 64, 3), 256>>>(
        x, Wq, bq, Qp, Wk, bk, Kp, Wv, bv, Vp);

    score_kernel<<<dim3(NTRI, NH, BATCH), 256>>>(Qp, Kp, Sp);
    select_kernel<<<dim3(SEQ / 8, NH, BATCH), 256>>>(Sp, Vp, HOp, Wp, Ip);

    float* yout = (float*)d_out;
    gemm_kernel<<<g64, 256>>>(HOp, Wo, bo, yout, MROWS, DM, DM);

    size_t ysz = (size_t)BATCH * SEQ * DM;          // 4,194,304
    size_t asz = (size_t)BATCH * SEQ * SEQ;         // 8,388,608
    if ((size_t)out_size >= ysz + asz) {
        mean_kernel<<<dim3(SEQ, BATCH), 256>>>(Wp, Ip, (float*)d_out + ysz);
    }
}

// round 16
// speedup vs baseline: 1.2286x; 1.2286x over previous
#include <cuda_runtime.h>
#include <cuda_bf16.h>

#define BATCH 2
#define SEQ   2048
#define DM    1024
#define NH    16
#define DH    64
#define KS    32

#define MROWS (BATCH*SEQ)   // 4096
#define FULLM 0xffffffffu
#define NTRI  136

// ---------------- scratch ----------------------------------------------------
__device__ float g_Q [BATCH*SEQ*DM];
__device__ float g_K [BATCH*SEQ*DM];
__device__ float g_V [BATCH*SEQ*DM];
__device__ float g_HO[BATCH*SEQ*DM];
__device__ float g_WGT[BATCH*NH*SEQ*KS];
__device__ int   g_IDX[BATCH*NH*SEQ*KS];
__device__ float g_SC[(size_t)BATCH*NH*SEQ*SEQ];

__device__ __forceinline__ float neg_inf() { return __int_as_float(0xff800000); }

// ---------------- 128x128 fp32 GEMM core (round-14 proven): ------------------
// C = A @ W^T + bias. BK=16 double-buffered, register prefetch, 8x8 microtile.
#define BM 128
#define BN 128
#define BK2 16

__device__ __forceinline__ void gemm128_tile(
    const float* __restrict__ A, const float* __restrict__ W,
    const float* __restrict__ bias, float* __restrict__ C,
    int M, int N, int K, int bm, int bn)
{
    __shared__ float As[2][BK2][BM];
    __shared__ float Ws[2][BK2][BN];
    const int tid = threadIdx.x;
    const int tx = tid & 15, ty = tid >> 4;

    float acc[8][8];
#pragma unroll
    for (int i = 0; i < 8; i++)
#pragma unroll
        for (int j = 0; j < 8; j++) acc[i][j] = 0.f;

    const int lr = tid >> 1;            // 0..127
    const int lc = (tid & 1) * 8;       // 0 or 8

    const float* Ap = A + (size_t)(bm + lr) * K + lc;
    const float* Wp = W + (size_t)(bn + lr) * K + lc;

    float4 pa0 = *(const float4*)(Ap);
    float4 pa1 = *(const float4*)(Ap + 4);
    float4 pw0 = *(const float4*)(Wp);
    float4 pw1 = *(const float4*)(Wp + 4);

    As[0][lc+0][lr]=pa0.x; As[0][lc+1][lr]=pa0.y; As[0][lc+2][lr]=pa0.z; As[0][lc+3][lr]=pa0.w;
    As[0][lc+4][lr]=pa1.x; As[0][lc+5][lr]=pa1.y; As[0][lc+6][lr]=pa1.z; As[0][lc+7][lr]=pa1.w;
    Ws[0][lc+0][lr]=pw0.x; Ws[0][lc+1][lr]=pw0.y; Ws[0][lc+2][lr]=pw0.z; Ws[0][lc+3][lr]=pw0.w;
    Ws[0][lc+4][lr]=pw1.x; Ws[0][lc+5][lr]=pw1.y; Ws[0][lc+6][lr]=pw1.z; Ws[0][lc+7][lr]=pw1.w;
    __syncthreads();

    const int ntile = K / BK2;
    for (int t = 0; t < ntile; t++) {
        const int buf = t & 1;
        const bool more = (t + 1 < ntile);
        if (more) {
            pa0 = *(const float4*)(Ap + (t + 1) * BK2);
            pa1 = *(const float4*)(Ap + (t + 1) * BK2 + 4);
            pw0 = *(const float4*)(Wp + (t + 1) * BK2);
            pw1 = *(const float4*)(Wp + (t + 1) * BK2 + 4);
        }
#pragma unroll
        for (int kk = 0; kk < BK2; kk++) {
            float4 a0 = *(const float4*)&As[buf][kk][ty*4];
            float4 a1 = *(const float4*)&As[buf][kk][64 + ty*4];
            float4 w0 = *(const float4*)&Ws[buf][kk][tx*4];
            float4 w1 = *(const float4*)&Ws[buf][kk][64 + tx*4];
            float a[8] = {a0.x,a0.y,a0.z,a0.w,a1.x,a1.y,a1.z,a1.w};
            float w[8] = {w0.x,w0.y,w0.z,w0.w,w1.x,w1.y,w1.z,w1.w};
#pragma unroll
            for (int i = 0; i < 8; i++)
#pragma unroll
                for (int j = 0; j < 8; j++)
                    acc[i][j] += a[i] * w[j];
        }
        if (more) {
            const int nb = buf ^ 1;
            As[nb][lc+0][lr]=pa0.x; As[nb][lc+1][lr]=pa0.y; As[nb][lc+2][lr]=pa0.z; As[nb][lc+3][lr]=pa0.w;
            As[nb][lc+4][lr]=pa1.x; As[nb][lc+5][lr]=pa1.y; As[nb][lc+6][lr]=pa1.z; As[nb][lc+7][lr]=pa1.w;
            Ws[nb][lc+0][lr]=pw0.x; Ws[nb][lc+1][lr]=pw0.y; Ws[nb][lc+2][lr]=pw0.z; Ws[nb][lc+3][lr]=pw0.w;
            Ws[nb][lc+4][lr]=pw1.x; Ws[nb][lc+5][lr]=pw1.y; Ws[nb][lc+6][lr]=pw1.z; Ws[nb][lc+7][lr]=pw1.w;
        }
        __syncthreads();
    }

    float4 b0 = *(const float4*)(bias + bn + tx*4);
    float4 b1 = *(const float4*)(bias + bn + 64 + tx*4);
    float bb[8] = {b0.x,b0.y,b0.z,b0.w,b1.x,b1.y,b1.z,b1.w};

#pragma unroll
    for (int i = 0; i < 8; i++) {
        int m = bm + ((i < 4) ? (ty*4 + i) : (64 + ty*4 + i - 4));
        float4 o0 = make_float4(acc[i][0]+bb[0], acc[i][1]+bb[1], acc[i][2]+bb[2], acc[i][3]+bb[3]);
        float4 o1 = make_float4(acc[i][4]+bb[4], acc[i][5]+bb[5], acc[i][6]+bb[6], acc[i][7]+bb[7]);
        *(float4*)(C + (size_t)m * N + bn + tx*4)      = o0;
        *(float4*)(C + (size_t)m * N + bn + 64 + tx*4) = o1;
    }
}

// ---------------- fused QKV projection (grid.z selects Q/K/V) ----------------
__global__ __launch_bounds__(256) void qkv_kernel(
    const float* __restrict__ x,
    const float* __restrict__ Wq, const float* __restrict__ bq, float* __restrict__ Qo,
    const float* __restrict__ Wk, const float* __restrict__ bk, float* __restrict__ Ko,
    const float* __restrict__ Wv, const float* __restrict__ bv, float* __restrict__ Vo)
{
    const float* W; const float* bias; float* C;
    if (blockIdx.z == 0)      { W = Wq; bias = bq; C = Qo; }
    else if (blockIdx.z == 1) { W = Wk; bias = bk; C = Ko; }
    else                      { W = Wv; bias = bv; C = Vo; }
    gemm128_tile(x, W, bias, C, MROWS, DM, DM,
                 blockIdx.y * BM, blockIdx.x * BN);
}

// ---------------- output projection ------------------------------------------
__global__ __launch_bounds__(256) void gemm_kernel(
    const float* __restrict__ A, const float* __restrict__ W,
    const float* __restrict__ bias, float* __restrict__ C,
    int M, int N, int K)
{
    gemm128_tile(A, W, bias, C, M, N, K, blockIdx.y * BM, blockIdx.x * BN);
}

// ---------------- score GEMM: S[q,k] = (Q_row_q . K_row_k) / 8 ---------------
__global__ __launch_bounds__(256) void score_kernel(
    const float* __restrict__ Q, const float* __restrict__ Kg,
    float* __restrict__ SC)
{
    __shared__ float As[16][BM];
    __shared__ float Ws[16][BN];

    const int t = blockIdx.x;
    const int h = blockIdx.y, b = blockIdx.z;
    int qt = (int)((sqrtf(8.f * t + 1.f) - 1.f) * 0.5f);
    while ((qt + 1) * (qt + 2) / 2 <= t) qt++;
    while (qt * (qt + 1) / 2 > t) qt--;
    int kt = t - qt * (qt + 1) / 2;

    const int tid = threadIdx.x;
    const int tx = tid & 15, ty = tid >> 4;
    const int bm = qt * BM, bn = kt * BN;

    float acc[8][8];
#pragma unroll
    for (int i = 0; i < 8; i++)
#pragma unroll
        for (int j = 0; j < 8; j++) acc[i][j] = 0.f;

    const float* Qb = Q  + (size_t)b*SEQ*DM + h*DH;
    const float* Kb = Kg + (size_t)b*SEQ*DM + h*DH;

    int lr = tid >> 1;            // 0..127
    int lc = (tid & 1) * 8;       // 0 or 8

    for (int k0 = 0; k0 < DH; k0 += 16) {
        float4 a0 = *(const float4*)(Qb + (size_t)(bm + lr) * DM + k0 + lc);
        float4 a1 = *(const float4*)(Qb + (size_t)(bm + lr) * DM + k0 + lc + 4);
        float4 w0 = *(const float4*)(Kb + (size_t)(bn + lr) * DM + k0 + lc);
        float4 w1 = *(const float4*)(Kb + (size_t)(bn + lr) * DM + k0 + lc + 4);
        As[lc+0][lr]=a0.x; As[lc+1][lr]=a0.y; As[lc+2][lr]=a0.z; As[lc+3][lr]=a0.w;
        As[lc+4][lr]=a1.x; As[lc+5][lr]=a1.y; As[lc+6][lr]=a1.z; As[lc+7][lr]=a1.w;
        Ws[lc+0][lr]=w0.x; Ws[lc+1][lr]=w0.y; Ws[lc+2][lr]=w0.z; Ws[lc+3][lr]=w0.w;
        Ws[lc+4][lr]=w1.x; Ws[lc+5][lr]=w1.y; Ws[lc+6][lr]=w1.z; Ws[lc+7][lr]=w1.w;
        __syncthreads();
#pragma unroll
        for (int kk = 0; kk < 16; kk++) {
            float4 q0 = *(const float4*)&As[kk][ty*4];
            float4 q1 = *(const float4*)&As[kk][64 + ty*4];
            float4 k0v = *(const float4*)&Ws[kk][tx*4];
            float4 k1v = *(const float4*)&Ws[kk][64 + tx*4];
            float a[8] = {q0.x,q0.y,q0.z,q0.w,q1.x,q1.y,q1.z,q1.w};
            float w[8] = {k0v.x,k0v.y,k0v.z,k0v.w,k1v.x,k1v.y,k1v.z,k1v.w};
#pragma unroll
            for (int i = 0; i < 8; i++)
#pragma unroll
                for (int j = 0; j < 8; j++)
                    acc[i][j] += a[i] * w[j];
        }
        __syncthreads();
    }

    float* Sb = SC + (((size_t)b*NH + h)*SEQ) * SEQ;
#pragma unroll
    for (int i = 0; i < 8; i++) {
        int m = bm + ((i < 4) ? (ty*4 + i) : (64 + ty*4 + i - 4));
        float4 o0 = make_float4(acc[i][0]*.125f, acc[i][1]*.125f, acc[i][2]*.125f, acc[i][3]*.125f);
        float4 o1 = make_float4(acc[i][4]*.125f, acc[i][5]*.125f, acc[i][6]*.125f, acc[i][7]*.125f);
        *(float4*)(Sb + (size_t)m * SEQ + bn + tx*4)      = o0;
        *(float4*)(Sb + (size_t)m * SEQ + bn + 64 + tx*4) = o1;
    }
}

// ---------------- selection: streaming top-32 (pipelined f4) + softmax + AV --
__global__ __launch_bounds__(256) void select_kernel(
    const float* __restrict__ SC, const float* __restrict__ Vg,
    float* __restrict__ HO, float* __restrict__ WGT, int* __restrict__ IDX)
{
    const int h = blockIdx.y, b = blockIdx.z;
    const int tid = threadIdx.x;
    const int lane = tid & 31, wid = tid >> 5;
    const int q = blockIdx.x * 8 + wid;
    const float NEG = neg_inf();

    const float* row = SC + ((((size_t)b*NH + h)*SEQ) + q) * SEQ;

    float sv = NEG;
    int   si = 0x7fffffff;
    float minv = NEG;
    int   mini = 0x7fffffff;

    const int total = q + 1;
    const int ngrp = total >> 7;              // full 128-key groups

    float4 cur;
    if (ngrp > 0) cur = *(const float4*)(row + lane * 4);

    for (int g = 0; g < ngrp; g++) {
        float4 nxt;
        if (g + 1 < ngrp)
            nxt = *(const float4*)(row + (g + 1) * 128 + lane * 4);
        const int base = g * 128 + lane * 4;
#pragma unroll
        for (int j = 0; j < 4; j++) {
            float v = (j == 0) ? cur.x : (j == 1) ? cur.y : (j == 2) ? cur.z : cur.w;
            int ii = base + j;
            bool contend = (v > minv) || (v == minv && ii < mini);
            unsigned m = __ballot_sync(FULLM, contend);
            if (m) {
                do {
                    int src = __ffs(m) - 1; m &= m - 1;
                    float nv = __shfl_sync(FULLM, v,  src);
                    int   ni = __shfl_sync(FULLM, ii, src);
                    bool better = (nv < sv) || (nv == sv && si < ni);  // sv better
                    unsigned bm2 = __ballot_sync(FULLM, better);
                    int p = __popc(bm2);
                    float upv = __shfl_up_sync(FULLM, sv, 1);
                    int   upi = __shfl_up_sync(FULLM, si, 1);
                    if (lane == p)      { sv = nv;  si = ni;  }
                    else if (lane > p)  { sv = upv; si = upi; }
                } while (m);
                minv = __shfl_sync(FULLM, sv, 31);
                mini = __shfl_sync(FULLM, si, 31);
            }
        }
        cur = nxt;
    }

    // tail: keys [ngrp*128, total)
    for (int k0 = ngrp << 7; k0 < total; k0 += 32) {
        int k = k0 + lane;
        float v = NEG; int ii = 0x7fffffff;
        if (k < total) { v = row[k]; ii = k; }

        bool contend = (v > minv) || (v == minv && v != NEG && ii < mini);
        unsigned m = __ballot_sync(FULLM, contend);
        if (m) {
            do {
                int src = __ffs(m) - 1; m &= m - 1;
                float nv = __shfl_sync(FULLM, v,  src);
                int   ni = __shfl_sync(FULLM, ii, src);
                bool better = (sv > nv) || (sv == nv && si < ni);
                unsigned bm2 = __ballot_sync(FULLM, better);
                int p = __popc(bm2);
                float upv = __shfl_up_sync(FULLM, sv, 1);
                int   upi = __shfl_up_sync(FULLM, si, 1);
                if (lane == p)      { sv = nv;  si = ni;  }
                else if (lane > p)  { sv = upv; si = upi; }
            } while (m);
            minv = __shfl_sync(FULLM, sv, 31);
            mini = __shfl_sync(FULLM, si, 31);
        }
    }

    // softmax over selected (sorted descending; lane 0 = max, finite)
    bool valid = (sv != NEG);
    float mx = __shfl_sync(FULLM, sv, 0);
    float e = valid ? expf(sv - mx) : 0.f;
    float tot = e;
#pragma unroll
    for (int o = 16; o; o >>= 1) tot += __shfl_xor_sync(FULLM, tot, o);
    float w = e / tot;
    int iw = valid ? si : -1;

    size_t off = ((((size_t)b*NH + h)*SEQ) + (size_t)q) * KS + lane;
    WGT[off] = w;
    IDX[off] = iw;

    // AV: each lane owns dims (lane, lane+32)
    const float* Vb = Vg + (size_t)b*SEQ*DM + h*DH;
    float acc0 = 0.f, acc1 = 0.f;
#pragma unroll
    for (int j = 0; j < KS; j++) {
        float wj = __shfl_sync(FULLM, w, j);
        int   ij = __shfl_sync(FULLM, iw, j);
        if (ij >= 0) {
            const float* vr = Vb + (size_t)ij * DM;
            acc0 += wj * vr[lane];
            acc1 += wj * vr[lane + 32];
        }
    }
    float* out = HO + ((size_t)(b*SEQ + q)) * DM + h*DH;
    out[lane]      = acc0;
    out[lane + 32] = acc1;
}

// ---------------- mean over heads -> dense [B, SEQ, SEQ] ---------------------
__global__ __launch_bounds__(256) void mean_kernel(
    const float* __restrict__ WGT, const int* __restrict__ IDX,
    float* __restrict__ out_attn)
{
    __shared__ float row[SEQ];
    const int q = blockIdx.x, b = blockIdx.y;
    const int tid = threadIdx.x;
    for (int i = tid; i < SEQ; i += 256) row[i] = 0.f;
    __syncthreads();
    for (int h = 0; h < NH; h++) {
        if (tid < KS) {
            size_t off = ((((size_t)b*NH + h)*SEQ) + q) * KS + tid;
            float w = WGT[off];
            int k = IDX[off];
            if (k >= 0 && w > 0.f) row[k] += w * (1.0f / NH);
        }
        __syncthreads();
    }
    float* o = out_attn + ((size_t)b*SEQ + q) * SEQ;
    for (int i = tid; i < SEQ; i += 256) o[i] = row[i];
}

// ---------------- launch -----------------------------------------------------
extern "C" void kernel_launch(void* const* d_in, const int* in_sizes, int n_in,
                              void* d_out, int out_size)
{
    const float* x  = (const float*)d_in[0];
    const float* Wq = (const float*)d_in[1];
    const float* bq = (const float*)d_in[2];
    const float* Wk = (const float*)d_in[3];
    const float* bk = (const float*)d_in[4];
    const float* Wv = (const float*)d_in[5];
    const float* bv = (const float*)d_in[6];
    const float* Wo = (const float*)d_in[7];
    const float* bo = (const float*)d_in[8];

    float *Qp, *Kp, *Vp, *HOp, *Wp, *Sp; int* Ip;
    cudaGetSymbolAddress((void**)&Qp,  g_Q);
    cudaGetSymbolAddress((void**)&Kp,  g_K);
    cudaGetSymbolAddress((void**)&Vp,  g_V);
    cudaGetSymbolAddress((void**)&HOp, g_HO);
    cudaGetSymbolAddress((void**)&Wp,  g_WGT);
    cudaGetSymbolAddress((void**)&Ip,  g_IDX);
    cudaGetSymbolAddress((void**)&Sp,  g_SC);

    // fused QKV: one launch, 768 blocks -> single partial tail wave
    qkv_kernel<<<dim3(DM / BN, MROWS / BM, 3), 256>>>(
        x, Wq, bq, Qp, Wk, bk, Kp, Wv, bv, Vp);

    score_kernel<<<dim3(NTRI, NH, BATCH), 256>>>(Qp, Kp, Sp);
    select_kernel<<<dim3(SEQ / 8, NH, BATCH), 256>>>(Sp, Vp, HOp, Wp, Ip);

    float* yout = (float*)d_out;
    gemm_kernel<<<dim3(DM / BN, MROWS / BM), 256>>>(HOp, Wo, bo, yout, MROWS, DM, DM);

    size_t ysz = (size_t)BATCH * SEQ * DM;          // 4,194,304
    size_t asz = (size_t)BATCH * SEQ * SEQ;         // 8,388,608
    if ((size_t)out_size >= ysz + asz) {
        mean_kernel<<<dim3(SEQ, BATCH), 256>>>(Wp, Ip, (float*)d_out + ysz);
    }
}